// round 7
// baseline (speedup 1.0000x reference)
#include <cuda_runtime.h>
#include <cuda_fp16.h>
#include <cstdint>

// Problem constants
#define BN 8
#define CCH 128
#define HH 128
#define WW 256
#define NI 65

// Tiling
#define WT 64
#define KC 32
#define LDA 72      // X1s stride in halves
#define LDB 136     // X2s stride in halves
#define LDJ 68      // cs2 stride in floats (272B = 17*16: float4-aligned, STS conflict-free)
#define JPAD 15     // staged j in [-15, 79] -> 95 rows, pads never read

#define X1BUF (KC * LDA)
#define X2BUF (KC * LDB)
#define X1_BYTES (2 * X1BUF * 2)                  // 9216
#define X2_BYTES (2 * X2BUF * 2)                  // 17408
#define CS_OFF (X1_BYTES + X2_BYTES)              // 26624 (16B aligned)
#define SMEM_TOTAL (CS_OFF + 95 * LDJ * 4)        // 52464 B

#define GRIDX 592                      // 148 SMs x 4 resident CTAs (persistent)
#define NTILES (BN * HH * (WW / WT))   // 4096

__global__ __launch_bounds__(256, 4)
void corr_volume_kernel(const float* __restrict__ x1,
                        const float* __restrict__ x2,
                        float* __restrict__ out)
{
    extern __shared__ __align__(16) char smraw[];
    __half (*X1s)[X1BUF] = (__half(*)[X1BUF])smraw;
    __half (*X2s)[X2BUF] = (__half(*)[X2BUF])(smraw + X1_BYTES);
    float* cs2 = (float*)(smraw + CS_OFF);

    const int tid  = threadIdx.x;
    const int lane = tid & 31;
    const int wid  = tid >> 5;
    // 4x2 banded warp grid: warp (wm, wn) -> rows [m0, m0+16), band cols [nst, nst+40)
    const int wm   = wid >> 1;
    const int wn   = wid & 1;
    const int m0   = wm * 16;
    const int nst  = m0 + wn * 40;

    const uint32_t x1s_base = (uint32_t)__cvta_generic_to_shared(X1s);
    const uint32_t x2s_base = (uint32_t)__cvta_generic_to_shared(X2s);
    const int r = lane & 7;
    const uint32_t addrA0 = x1s_base +
        2u * ((uint32_t)((r + ((lane >> 4) & 1) * 8) * LDA + (m0 + ((lane >> 3) & 1) * 8)));
    const uint32_t addrB0 = x2s_base +
        2u * ((uint32_t)((r + ((lane >> 3) & 1) * 8) * LDB + (nst + ((lane >> 4) & 1) * 8)));

    const size_t cstride = (size_t)HH * WW;

    // fixed per-thread load coordinates
    const int cr1a = tid >> 4;            // X1 row of 1st float4
    const int co1  = (tid & 15) * 4;
    const int cr2a = tid >> 5;            // X2 row of 1st float4
    const int co2  = (tid & 31) * 4;

    float acc[5][4];
    float4 p1[2], p2[4];

    auto tile_x1p = [&](int t) -> const float* {
        int bx = t & 3, h = (t >> 2) & (HH - 1), n = t >> 9;
        return x1 + ((size_t)n * CCH * HH + (size_t)h) * WW + bx * WT;
    };
    auto tile_x2p = [&](int t) -> const float* {
        int bx = t & 3, h = (t >> 2) & (HH - 1), n = t >> 9;
        return x2 + ((size_t)n * CCH * HH + (size_t)h) * WW + (bx * WT - 64);
    };

    auto load_chunk = [&](const float* x1p, const float* x2p, bool ok, int kc) {
        #pragma unroll
        for (int it = 0; it < 2; it++)
            p1[it] = *(const float4*)(x1p + (size_t)(kc * KC + cr1a + it * 16) * cstride + co1);
        #pragma unroll
        for (int it = 0; it < 4; it++) {
            if (ok)
                p2[it] = *(const float4*)(x2p + (size_t)(kc * KC + cr2a + it * 8) * cstride + co2);
            else
                p2[it] = make_float4(0.f, 0.f, 0.f, 0.f);
        }
    };
    auto store_chunk = [&](int buf) {
        #pragma unroll
        for (int it = 0; it < 2; it++) {
            __half2* d = (__half2*)&X1s[buf][(cr1a + it * 16) * LDA + co1];
            d[0] = __floats2half2_rn(p1[it].x, p1[it].y);
            d[1] = __floats2half2_rn(p1[it].z, p1[it].w);
        }
        #pragma unroll
        for (int it = 0; it < 4; it++) {
            __half2* d = (__half2*)&X2s[buf][(cr2a + it * 8) * LDB + co2];
            d[0] = __floats2half2_rn(p2[it].x, p2[it].y);
            d[1] = __floats2half2_rn(p2[it].z, p2[it].w);
        }
    };

    int t = blockIdx.x;
    if (t >= NTILES) return;

    const float* x1p = tile_x1p(t);
    const float* x2p = tile_x2p(t);
    bool ok = ((t & 3) != 0) || (co2 >= 64);

    // prologue: chunk0 -> buf0; chunk1 held in regs (stored at kc=0)
    load_chunk(x1p, x2p, ok, 0);
    store_chunk(0);
    load_chunk(x1p, x2p, ok, 1);
    __syncthreads();

    while (true) {
        const int tn = t + GRIDX;
        const bool has_next = (tn < NTILES);
        const float* x1pN = has_next ? tile_x1p(tn) : x1p;
        const float* x2pN = has_next ? tile_x2p(tn) : x2p;
        const bool okN = has_next ? (((tn & 3) != 0) || (co2 >= 64)) : false;

        #pragma unroll
        for (int i5 = 0; i5 < 5; i5++)
            #pragma unroll
            for (int j = 0; j < 4; j++) acc[i5][j] = 0.f;

        // Deferred-store pipeline. Entry: buf0 = chunk0, regs = chunk1.
        //  kc: store held regs -> buf((kc+1)&1); issue loads for chunk kc+2
        //      (kc==2 loads next tile's chunk0); MMA on buf(kc&1); sync.
        #pragma unroll
        for (int kc = 0; kc < 4; kc++) {
            if (kc < 3)
                store_chunk((kc + 1) & 1);
            else if (has_next)
                store_chunk(0);                  // next tile's chunk0 -> buf0

            if (kc < 2)
                load_chunk(x1p, x2p, ok, kc + 2);
            else if (kc == 2 && has_next)
                load_chunk(x1pN, x2pN, okN, 0);

            const uint32_t offA = (uint32_t)((kc & 1) * X1BUF * 2);
            const uint32_t offB = (uint32_t)((kc & 1) * X2BUF * 2);

            #pragma unroll
            for (int ks = 0; ks < KC / 16; ks++) {
                uint32_t a[4];
                {
                    uint32_t aaddr = addrA0 + offA + 2u * (uint32_t)(ks * 16 * LDA);
                    asm volatile(
                        "ldmatrix.sync.aligned.m8n8.x4.trans.shared.b16 {%0,%1,%2,%3}, [%4];\n"
                        : "=r"(a[0]), "=r"(a[1]), "=r"(a[2]), "=r"(a[3]) : "r"(aaddr));
                }
                #pragma unroll
                for (int p = 0; p < 2; p++) {
                    uint32_t b0, b1, b2, b3;
                    uint32_t baddr = addrB0 + offB + 2u * (uint32_t)(ks * 16 * LDB + p * 16);
                    asm volatile(
                        "ldmatrix.sync.aligned.m8n8.x4.trans.shared.b16 {%0,%1,%2,%3}, [%4];\n"
                        : "=r"(b0), "=r"(b1), "=r"(b2), "=r"(b3) : "r"(baddr));
                    asm volatile(
                        "mma.sync.aligned.m16n8k16.row.col.f32.f16.f16.f32 "
                        "{%0,%1,%2,%3}, {%4,%5,%6,%7}, {%8,%9}, {%0,%1,%2,%3};\n"
                        : "+f"(acc[2*p][0]), "+f"(acc[2*p][1]), "+f"(acc[2*p][2]), "+f"(acc[2*p][3])
                        : "r"(a[0]), "r"(a[1]), "r"(a[2]), "r"(a[3]), "r"(b0), "r"(b1));
                    asm volatile(
                        "mma.sync.aligned.m16n8k16.row.col.f32.f16.f16.f32 "
                        "{%0,%1,%2,%3}, {%4,%5,%6,%7}, {%8,%9}, {%0,%1,%2,%3};\n"
                        : "+f"(acc[2*p+1][0]), "+f"(acc[2*p+1][1]), "+f"(acc[2*p+1][2]), "+f"(acc[2*p+1][3])
                        : "r"(a[0]), "r"(a[1]), "r"(a[2]), "r"(a[3]), "r"(b2), "r"(b3));
                }
                {
                    uint32_t b0, b1;
                    uint32_t baddr = addrB0 + offB + 2u * (uint32_t)(ks * 16 * LDB + 32);
                    asm volatile(
                        "ldmatrix.sync.aligned.m8n8.x2.trans.shared.b16 {%0,%1}, [%2];\n"
                        : "=r"(b0), "=r"(b1) : "r"(baddr));
                    asm volatile(
                        "mma.sync.aligned.m16n8k16.row.col.f32.f16.f16.f32 "
                        "{%0,%1,%2,%3}, {%4,%5,%6,%7}, {%8,%9}, {%0,%1,%2,%3};\n"
                        : "+f"(acc[4][0]), "+f"(acc[4][1]), "+f"(acc[4][2]), "+f"(acc[4][3])
                        : "r"(a[0]), "r"(a[1]), "r"(a[2]), "r"(a[3]), "r"(b0), "r"(b1));
                }
            }
            __syncthreads();
        }

        // ---- epilogue: next chunk1 LDGs in flight under staging + output ----
        if (has_next)
            load_chunk(x1pN, x2pN, okN, 1);      // held; stored at next tile's kc=0

        // unconditional band staging: cs2[(j+15)*LDJ + row], j = col - row
        {
            const int rowa = m0 + (lane >> 2);
            #pragma unroll
            for (int t8 = 0; t8 < 5; t8++) {
                int colb = nst + t8 * 8 + 2 * (lane & 3);
                #pragma unroll
                for (int e = 0; e < 2; e++) {
                    cs2[(colb + e - rowa + JPAD) * LDJ + rowa]         = acc[t8][e];
                    cs2[(colb + e - rowa - 8 + JPAD) * LDJ + rowa + 8] = acc[t8][2 + e];
                }
            }
        }
        __syncthreads();

        // ---- vectorized de-band: out[n,i,h,w0+4q..+3] = cs2[(79-i)*LDJ + 4q..] /128
        {
            const int bx = t & 3, h = (t >> 2) & (HH - 1), n = t >> 9;
            const int q    = tid & 15;
            const int rowi = tid >> 4;            // 0..15
            float* ob = out + (((size_t)n * NI) * HH + h) * WW + bx * WT + 4 * q;
            #pragma unroll
            for (int it = 0; it < 5; it++) {
                int i = it * 16 + rowi;
                if (i < NI) {
                    float4 v = *(const float4*)(cs2 + (79 - i) * LDJ + 4 * q);
                    v.x *= (1.0f / 128.0f); v.y *= (1.0f / 128.0f);
                    v.z *= (1.0f / 128.0f); v.w *= (1.0f / 128.0f);
                    *(float4*)(ob + (size_t)i * HH * WW) = v;
                }
            }
        }
        // cs2 reads complete before any warp's next staging (4 syncs away).

        if (!has_next) break;
        t = tn;
        x1p = x1pN; x2p = x2pN; ok = okN;
    }
}

extern "C" void kernel_launch(void* const* d_in, const int* in_sizes, int n_in,
                              void* d_out, int out_size)
{
    const float* x1 = (const float*)d_in[0];
    const float* x2 = (const float*)d_in[1];
    float* out = (float*)d_out;
    (void)in_sizes; (void)n_in; (void)out_size;

    cudaFuncSetAttribute(corr_volume_kernel,
                         cudaFuncAttributeMaxDynamicSharedMemorySize, SMEM_TOTAL);

    dim3 grid(GRIDX);
    dim3 block(256);
    corr_volume_kernel<<<grid, block, SMEM_TOTAL>>>(x1, x2, out);
}

// round 8
// speedup vs baseline: 1.0459x; 1.0459x over previous
#include <cuda_runtime.h>
#include <cuda_fp16.h>
#include <cstdint>

// Problem constants
#define BN 8
#define CCH 128
#define HH 128
#define WW 256
#define NI 65

// Tiling
#define WT 64
#define KC 32
#define LDA 72      // X1s stride in halves
#define LDB 136     // X2s stride in halves
#define LDJ 68      // cs2 stride in floats (272B = 17*16 -> float4-aligned rows, STS conflict-free)
#define JPAD 15     // staged j in [-15, 79] -> 95 rows; pads never read

#define X1BUF (KC * LDA)
#define X2BUF (KC * LDB)
#define X1_BYTES (2 * X1BUF * 2)                  // 9216
#define X2_BYTES (2 * X2BUF * 2)                  // 17408
#define CS_OFF (X1_BYTES + X2_BYTES)              // 26624 (16B aligned)
#define SMEM_TOTAL (CS_OFF + 95 * LDJ * 4)        // 52464 B

#define GRIDX 592                      // 148 SMs x 4 resident CTAs (persistent)
#define NTILES (BN * HH * (WW / WT))   // 4096

__global__ __launch_bounds__(256, 4)
void corr_volume_kernel(const float* __restrict__ x1,
                        const float* __restrict__ x2,
                        float* __restrict__ out)
{
    extern __shared__ __align__(16) char smraw[];
    __half (*X1s)[X1BUF] = (__half(*)[X1BUF])smraw;
    __half (*X2s)[X2BUF] = (__half(*)[X2BUF])(smraw + X1_BYTES);
    float* cs2 = (float*)(smraw + CS_OFF);

    const int tid  = threadIdx.x;
    const int lane = tid & 31;
    const int wid  = tid >> 5;
    // 4x2 banded warp grid: warp (wm, wn) -> rows [m0, m0+16), band cols [nst, nst+40)
    const int wm   = wid >> 1;
    const int wn   = wid & 1;
    const int m0   = wm * 16;
    const int nst  = m0 + wn * 40;

    const uint32_t x1s_base = (uint32_t)__cvta_generic_to_shared(X1s);
    const uint32_t x2s_base = (uint32_t)__cvta_generic_to_shared(X2s);
    const int r = lane & 7;
    const uint32_t addrA0 = x1s_base +
        2u * ((uint32_t)((r + ((lane >> 4) & 1) * 8) * LDA + (m0 + ((lane >> 3) & 1) * 8)));
    const uint32_t addrB0 = x2s_base +
        2u * ((uint32_t)((r + ((lane >> 3) & 1) * 8) * LDB + (nst + ((lane >> 4) & 1) * 8)));

    const size_t cstride = (size_t)HH * WW;

    // fixed per-thread load coordinates
    const int cr1a = tid >> 4;            // X1 row of 1st float4
    const int co1  = (tid & 15) * 4;
    const int cr2a = tid >> 5;            // X2 row of 1st float4
    const int co2  = (tid & 31) * 4;

    float acc[5][4];
    float4 p1[2], p2[4];

    auto tile_x1p = [&](int t) -> const float* {
        int bx = t & 3, h = (t >> 2) & (HH - 1), n = t >> 9;
        return x1 + ((size_t)n * CCH * HH + (size_t)h) * WW + bx * WT;
    };
    auto tile_x2p = [&](int t) -> const float* {
        int bx = t & 3, h = (t >> 2) & (HH - 1), n = t >> 9;
        return x2 + ((size_t)n * CCH * HH + (size_t)h) * WW + (bx * WT - 64);
    };

    auto load_chunk = [&](const float* x1p, const float* x2p, bool ok, int kc) {
        #pragma unroll
        for (int it = 0; it < 2; it++)
            p1[it] = *(const float4*)(x1p + (size_t)(kc * KC + cr1a + it * 16) * cstride + co1);
        #pragma unroll
        for (int it = 0; it < 4; it++) {
            if (ok)
                p2[it] = *(const float4*)(x2p + (size_t)(kc * KC + cr2a + it * 8) * cstride + co2);
            else
                p2[it] = make_float4(0.f, 0.f, 0.f, 0.f);
        }
    };
    auto store_chunk = [&](int buf) {
        #pragma unroll
        for (int it = 0; it < 2; it++) {
            __half2* d = (__half2*)&X1s[buf][(cr1a + it * 16) * LDA + co1];
            d[0] = __floats2half2_rn(p1[it].x, p1[it].y);
            d[1] = __floats2half2_rn(p1[it].z, p1[it].w);
        }
        #pragma unroll
        for (int it = 0; it < 4; it++) {
            __half2* d = (__half2*)&X2s[buf][(cr2a + it * 8) * LDB + co2];
            d[0] = __floats2half2_rn(p2[it].x, p2[it].y);
            d[1] = __floats2half2_rn(p2[it].z, p2[it].w);
        }
    };

    int t = blockIdx.x;
    if (t >= NTILES) return;

    const float* x1p = tile_x1p(t);
    const float* x2p = tile_x2p(t);
    bool ok = ((t & 3) != 0) || (co2 >= 64);

    // prologue: chunk 0 of first tile
    load_chunk(x1p, x2p, ok, 0);
    store_chunk(0);
    __syncthreads();

    while (true) {
        const int tn = t + GRIDX;
        const bool has_next = (tn < NTILES);
        const float* x1pN = has_next ? tile_x1p(tn) : x1p;
        const float* x2pN = has_next ? tile_x2p(tn) : x2p;
        const bool okN = has_next ? (((tn & 3) != 0) || (co2 >= 64)) : false;

        #pragma unroll
        for (int i5 = 0; i5 < 5; i5++)
            #pragma unroll
            for (int j = 0; j < 4; j++) acc[i5][j] = 0.f;

        // R6 pipeline: load at phase top (in flight under MMA), store at phase end,
        // nothing held across a __syncthreads.
        for (int kc = 0; kc < CCH / KC; kc++) {
            const int cur = kc & 1;
            const bool pf = (kc < CCH / KC - 1);
            if (pf)
                load_chunk(x1p, x2p, ok, kc + 1);
            else if (has_next)
                load_chunk(x1pN, x2pN, okN, 0);

            const uint32_t offA = (uint32_t)(cur * X1BUF * 2);
            const uint32_t offB = (uint32_t)(cur * X2BUF * 2);

            #pragma unroll
            for (int ks = 0; ks < KC / 16; ks++) {
                uint32_t a[4];
                {
                    uint32_t aaddr = addrA0 + offA + 2u * (uint32_t)(ks * 16 * LDA);
                    asm volatile(
                        "ldmatrix.sync.aligned.m8n8.x4.trans.shared.b16 {%0,%1,%2,%3}, [%4];\n"
                        : "=r"(a[0]), "=r"(a[1]), "=r"(a[2]), "=r"(a[3]) : "r"(aaddr));
                }
                #pragma unroll
                for (int p = 0; p < 2; p++) {
                    uint32_t b0, b1, b2, b3;
                    uint32_t baddr = addrB0 + offB + 2u * (uint32_t)(ks * 16 * LDB + p * 16);
                    asm volatile(
                        "ldmatrix.sync.aligned.m8n8.x4.trans.shared.b16 {%0,%1,%2,%3}, [%4];\n"
                        : "=r"(b0), "=r"(b1), "=r"(b2), "=r"(b3) : "r"(baddr));
                    asm volatile(
                        "mma.sync.aligned.m16n8k16.row.col.f32.f16.f16.f32 "
                        "{%0,%1,%2,%3}, {%4,%5,%6,%7}, {%8,%9}, {%0,%1,%2,%3};\n"
                        : "+f"(acc[2*p][0]), "+f"(acc[2*p][1]), "+f"(acc[2*p][2]), "+f"(acc[2*p][3])
                        : "r"(a[0]), "r"(a[1]), "r"(a[2]), "r"(a[3]), "r"(b0), "r"(b1));
                    asm volatile(
                        "mma.sync.aligned.m16n8k16.row.col.f32.f16.f16.f32 "
                        "{%0,%1,%2,%3}, {%4,%5,%6,%7}, {%8,%9}, {%0,%1,%2,%3};\n"
                        : "+f"(acc[2*p+1][0]), "+f"(acc[2*p+1][1]), "+f"(acc[2*p+1][2]), "+f"(acc[2*p+1][3])
                        : "r"(a[0]), "r"(a[1]), "r"(a[2]), "r"(a[3]), "r"(b2), "r"(b3));
                }
                {
                    uint32_t b0, b1;
                    uint32_t baddr = addrB0 + offB + 2u * (uint32_t)(ks * 16 * LDB + 32);
                    asm volatile(
                        "ldmatrix.sync.aligned.m8n8.x2.trans.shared.b16 {%0,%1}, [%2];\n"
                        : "=r"(b0), "=r"(b1) : "r"(baddr));
                    asm volatile(
                        "mma.sync.aligned.m16n8k16.row.col.f32.f16.f16.f32 "
                        "{%0,%1,%2,%3}, {%4,%5,%6,%7}, {%8,%9}, {%0,%1,%2,%3};\n"
                        : "+f"(acc[4][0]), "+f"(acc[4][1]), "+f"(acc[4][2]), "+f"(acc[4][3])
                        : "r"(a[0]), "r"(a[1]), "r"(a[2]), "r"(a[3]), "r"(b0), "r"(b1));
                }
            }

            if (pf || has_next)
                store_chunk((kc + 1) & 1);   // kc=3 stores next tile's chunk 0 into buf 0
            __syncthreads();
        }

        // ---- epilogue: unconditional padded band staging, cs2[(j+15)*LDJ + row] ----
        {
            const int rowa = m0 + (lane >> 2);
            #pragma unroll
            for (int t8 = 0; t8 < 5; t8++) {
                int colb = nst + t8 * 8 + 2 * (lane & 3);
                #pragma unroll
                for (int e = 0; e < 2; e++) {
                    cs2[(colb + e - rowa + JPAD) * LDJ + rowa]         = acc[t8][e];
                    cs2[(colb + e - rowa - 8 + JPAD) * LDJ + rowa + 8] = acc[t8][2 + e];
                }
            }
        }
        __syncthreads();

        // ---- vectorized de-band: out[n,i,h,w0+4q..] = cs2[(79-i)*LDJ + 4q..] / 128 ----
        {
            const int bx = t & 3, h = (t >> 2) & (HH - 1), n = t >> 9;
            const int q    = tid & 15;
            const int rowi = tid >> 4;            // 0..15
            float* ob = out + (((size_t)n * NI) * HH + h) * WW + bx * WT + 4 * q;
            #pragma unroll
            for (int it = 0; it < 5; it++) {
                int i = it * 16 + rowi;
                if (i < NI) {
                    float4 v = *(const float4*)(cs2 + (79 - i) * LDJ + 4 * q);
                    v.x *= (1.0f / 128.0f); v.y *= (1.0f / 128.0f);
                    v.z *= (1.0f / 128.0f); v.w *= (1.0f / 128.0f);
                    *(float4*)(ob + (size_t)i * HH * WW) = v;
                }
            }
        }
        // cs2 reads complete before any warp's next staging (4 chunk syncs away).

        if (!has_next) break;
        t = tn;
        x1p = x1pN; x2p = x2pN; ok = okN;
    }
}

extern "C" void kernel_launch(void* const* d_in, const int* in_sizes, int n_in,
                              void* d_out, int out_size)
{
    const float* x1 = (const float*)d_in[0];
    const float* x2 = (const float*)d_in[1];
    float* out = (float*)d_out;
    (void)in_sizes; (void)n_in; (void)out_size;

    cudaFuncSetAttribute(corr_volume_kernel,
                         cudaFuncAttributeMaxDynamicSharedMemorySize, SMEM_TOTAL);

    dim3 grid(GRIDX);
    dim3 block(256);
    corr_volume_kernel<<<grid, block, SMEM_TOTAL>>>(x1, x2, out);
}

// round 9
// speedup vs baseline: 1.4475x; 1.3840x over previous
#include <cuda_runtime.h>
#include <cuda_fp16.h>
#include <cstdint>

// Problem constants
#define BN 8
#define CCH 128
#define HH 128
#define WW 256
#define NI 65

// Tiling
#define WT 64
#define KC 32
#define LDA 72      // X1s stride in halves
#define LDB 136     // X2s stride in halves
#define LDJ 68      // cs2 stride in floats (272B = 17*16: float4-aligned, conflict-free)
#define JROWS 80    // cs2 rows; idx = (j+15) wrapped mod 80; valid j in [0,64] -> idx [15,79]

#define X1BUF (KC * LDA)
#define X2BUF (KC * LDB)

#define GRIDX 592                      // 148 SMs x 4 resident CTAs (persistent)
#define NTILES (BN * HH * (WW / WT))   // 4096

__global__ __launch_bounds__(256, 4)
void corr_volume_kernel(const float* __restrict__ x1,
                        const float* __restrict__ x2,
                        float* __restrict__ out)
{
    __shared__ __align__(16) __half X1s[2][X1BUF];     //  9216 B
    __shared__ __align__(16) __half X2s[2][X2BUF];     // 17408 B
    __shared__ __align__(16) float  cs2[JROWS * LDJ];  // 21760 B  (total 48384 <= 48K static)

    const int tid  = threadIdx.x;
    const int lane = tid & 31;
    const int wid  = tid >> 5;
    // 4x2 banded warp grid: warp (wm, wn) -> rows [m0, m0+16), band cols [nst, nst+40)
    const int wm   = wid >> 1;
    const int wn   = wid & 1;
    const int m0   = wm * 16;
    const int nst  = m0 + wn * 40;

    const uint32_t x1s_base = (uint32_t)__cvta_generic_to_shared(X1s);
    const uint32_t x2s_base = (uint32_t)__cvta_generic_to_shared(X2s);
    const int r = lane & 7;
    const uint32_t addrA0 = x1s_base +
        2u * ((uint32_t)((r + ((lane >> 4) & 1) * 8) * LDA + (m0 + ((lane >> 3) & 1) * 8)));
    const uint32_t addrB0 = x2s_base +
        2u * ((uint32_t)((r + ((lane >> 3) & 1) * 8) * LDB + (nst + ((lane >> 4) & 1) * 8)));

    const size_t cstride = (size_t)HH * WW;

    // fixed per-thread load coordinates
    const int cr1a = tid >> 4;            // X1 row of 1st float4
    const int co1  = (tid & 15) * 4;
    const int cr2a = tid >> 5;            // X2 row of 1st float4
    const int co2  = (tid & 31) * 4;

    float acc[5][4];
    float4 p1[2], p2[4];

    auto tile_x1p = [&](int t) -> const float* {
        int bx = t & 3, h = (t >> 2) & (HH - 1), n = t >> 9;
        return x1 + ((size_t)n * CCH * HH + (size_t)h) * WW + bx * WT;
    };
    auto tile_x2p = [&](int t) -> const float* {
        int bx = t & 3, h = (t >> 2) & (HH - 1), n = t >> 9;
        return x2 + ((size_t)n * CCH * HH + (size_t)h) * WW + (bx * WT - 64);
    };

    auto load_chunk = [&](const float* x1p, const float* x2p, bool ok, int kc) {
        #pragma unroll
        for (int it = 0; it < 2; it++)
            p1[it] = *(const float4*)(x1p + (size_t)(kc * KC + cr1a + it * 16) * cstride + co1);
        #pragma unroll
        for (int it = 0; it < 4; it++) {
            if (ok)
                p2[it] = *(const float4*)(x2p + (size_t)(kc * KC + cr2a + it * 8) * cstride + co2);
            else
                p2[it] = make_float4(0.f, 0.f, 0.f, 0.f);
        }
    };
    auto store_chunk = [&](int buf) {
        #pragma unroll
        for (int it = 0; it < 2; it++) {
            __half2* d = (__half2*)&X1s[buf][(cr1a + it * 16) * LDA + co1];
            d[0] = __floats2half2_rn(p1[it].x, p1[it].y);
            d[1] = __floats2half2_rn(p1[it].z, p1[it].w);
        }
        #pragma unroll
        for (int it = 0; it < 4; it++) {
            __half2* d = (__half2*)&X2s[buf][(cr2a + it * 8) * LDB + co2];
            d[0] = __floats2half2_rn(p2[it].x, p2[it].y);
            d[1] = __floats2half2_rn(p2[it].z, p2[it].w);
        }
    };

    int t = blockIdx.x;
    if (t >= NTILES) return;

    const float* x1p = tile_x1p(t);
    const float* x2p = tile_x2p(t);
    bool ok = ((t & 3) != 0) || (co2 >= 64);

    // prologue: chunk 0 of first tile
    load_chunk(x1p, x2p, ok, 0);
    store_chunk(0);
    __syncthreads();

    while (true) {
        const int tn = t + GRIDX;
        const bool has_next = (tn < NTILES);
        const float* x1pN = has_next ? tile_x1p(tn) : x1p;
        const float* x2pN = has_next ? tile_x2p(tn) : x2p;
        const bool okN = has_next ? (((tn & 3) != 0) || (co2 >= 64)) : false;

        #pragma unroll
        for (int i5 = 0; i5 < 5; i5++)
            #pragma unroll
            for (int j = 0; j < 4; j++) acc[i5][j] = 0.f;

        // R6 pipeline: load at phase top (in flight under MMA), store at phase end,
        // nothing held across a __syncthreads.
        for (int kc = 0; kc < CCH / KC; kc++) {
            const int cur = kc & 1;
            const bool pf = (kc < CCH / KC - 1);
            if (pf)
                load_chunk(x1p, x2p, ok, kc + 1);
            else if (has_next)
                load_chunk(x1pN, x2pN, okN, 0);

            const uint32_t offA = (uint32_t)(cur * X1BUF * 2);
            const uint32_t offB = (uint32_t)(cur * X2BUF * 2);

            #pragma unroll
            for (int ks = 0; ks < KC / 16; ks++) {
                uint32_t a[4];
                {
                    uint32_t aaddr = addrA0 + offA + 2u * (uint32_t)(ks * 16 * LDA);
                    asm volatile(
                        "ldmatrix.sync.aligned.m8n8.x4.trans.shared.b16 {%0,%1,%2,%3}, [%4];\n"
                        : "=r"(a[0]), "=r"(a[1]), "=r"(a[2]), "=r"(a[3]) : "r"(aaddr));
                }
                #pragma unroll
                for (int p = 0; p < 2; p++) {
                    uint32_t b0, b1, b2, b3;
                    uint32_t baddr = addrB0 + offB + 2u * (uint32_t)(ks * 16 * LDB + p * 16);
                    asm volatile(
                        "ldmatrix.sync.aligned.m8n8.x4.trans.shared.b16 {%0,%1,%2,%3}, [%4];\n"
                        : "=r"(b0), "=r"(b1), "=r"(b2), "=r"(b3) : "r"(baddr));
                    asm volatile(
                        "mma.sync.aligned.m16n8k16.row.col.f32.f16.f16.f32 "
                        "{%0,%1,%2,%3}, {%4,%5,%6,%7}, {%8,%9}, {%0,%1,%2,%3};\n"
                        : "+f"(acc[2*p][0]), "+f"(acc[2*p][1]), "+f"(acc[2*p][2]), "+f"(acc[2*p][3])
                        : "r"(a[0]), "r"(a[1]), "r"(a[2]), "r"(a[3]), "r"(b0), "r"(b1));
                    asm volatile(
                        "mma.sync.aligned.m16n8k16.row.col.f32.f16.f16.f32 "
                        "{%0,%1,%2,%3}, {%4,%5,%6,%7}, {%8,%9}, {%0,%1,%2,%3};\n"
                        : "+f"(acc[2*p+1][0]), "+f"(acc[2*p+1][1]), "+f"(acc[2*p+1][2]), "+f"(acc[2*p+1][3])
                        : "r"(a[0]), "r"(a[1]), "r"(a[2]), "r"(a[3]), "r"(b2), "r"(b3));
                }
                {
                    uint32_t b0, b1;
                    uint32_t baddr = addrB0 + offB + 2u * (uint32_t)(ks * 16 * LDB + 32);
                    asm volatile(
                        "ldmatrix.sync.aligned.m8n8.x2.trans.shared.b16 {%0,%1}, [%2];\n"
                        : "=r"(b0), "=r"(b1) : "r"(baddr));
                    asm volatile(
                        "mma.sync.aligned.m16n8k16.row.col.f32.f16.f16.f32 "
                        "{%0,%1,%2,%3}, {%4,%5,%6,%7}, {%8,%9}, {%0,%1,%2,%3};\n"
                        : "+f"(acc[4][0]), "+f"(acc[4][1]), "+f"(acc[4][2]), "+f"(acc[4][3])
                        : "r"(a[0]), "r"(a[1]), "r"(a[2]), "r"(a[3]), "r"(b0), "r"(b1));
                }
            }

            if (pf || has_next)
                store_chunk((kc + 1) & 1);   // kc=3 stores next tile's chunk 0 into buf 0
            __syncthreads();
        }

        // ---- epilogue: unconditional band staging with wrapped row index ----
        // idx = (col - row) + 15, wrapped into [0,80). Valid j in [0,64] -> idx [15,79],
        // never wrapped; all wrapped/pad writes land in idx [0,14], never read.
        {
            const int rowa = m0 + (lane >> 2);
            #pragma unroll
            for (int t8 = 0; t8 < 5; t8++) {
                int colb = nst + t8 * 8 + 2 * (lane & 3);
                int j0 = colb - rowa + 15;            // e=0, upper row
                int ja = j0;     if (ja >= JROWS) ja -= JROWS;
                int jb = j0 + 1; if (jb >= JROWS) jb -= JROWS;
                int jc = j0 - 8; if (jc >= JROWS) jc -= JROWS;
                int jd = j0 - 7; if (jd >= JROWS) jd -= JROWS;
                cs2[ja * LDJ + rowa]     = acc[t8][0];
                cs2[jb * LDJ + rowa]     = acc[t8][1];
                cs2[jc * LDJ + rowa + 8] = acc[t8][2];
                cs2[jd * LDJ + rowa + 8] = acc[t8][3];
            }
        }
        __syncthreads();

        // ---- vectorized de-band: out[n,i,h,w0+4q..] = cs2[(79-i)*LDJ + 4q..] / 128 ----
        {
            const int bx = t & 3, h = (t >> 2) & (HH - 1), n = t >> 9;
            const int q    = tid & 15;
            const int rowi = tid >> 4;            // 0..15
            float* ob = out + (((size_t)n * NI) * HH + h) * WW + bx * WT + 4 * q;
            #pragma unroll
            for (int it = 0; it < 5; it++) {
                int i = it * 16 + rowi;
                if (i < NI) {
                    float4 v = *(const float4*)(cs2 + (79 - i) * LDJ + 4 * q);
                    v.x *= (1.0f / 128.0f); v.y *= (1.0f / 128.0f);
                    v.z *= (1.0f / 128.0f); v.w *= (1.0f / 128.0f);
                    *(float4*)(ob + (size_t)i * HH * WW) = v;
                }
            }
        }
        // cs2 reads complete before any warp's next staging (4 chunk syncs away).

        if (!has_next) break;
        t = tn;
        x1p = x1pN; x2p = x2pN; ok = okN;
    }
}

extern "C" void kernel_launch(void* const* d_in, const int* in_sizes, int n_in,
                              void* d_out, int out_size)
{
    const float* x1 = (const float*)d_in[0];
    const float* x2 = (const float*)d_in[1];
    float* out = (float*)d_out;
    (void)in_sizes; (void)n_in; (void)out_size;

    dim3 grid(GRIDX);
    dim3 block(256);
    corr_volume_kernel<<<grid, block>>>(x1, x2, out);
}